// round 16
// baseline (speedup 1.0000x reference)
#include <cuda_runtime.h>

// Seq2Seq LSTM autoencoder, persistent-block, row-pair-packed f32x2, G=2.
// GB300: 152 SMs, 1 block/SM, 128 threads = 2 grps x 64 units, 1 warp/SMSP.
// Each thread owns 14 rows (7 f32x2 pairs): grp0 rows 0-13, grp1 rows 14-27.
// Halving the group count halves redundant weight re-reads (the measured L1
// bottleneck at G=4) while the per-SMSP FFMA2 floor stays 5376 cyc/step.
// State transposed: hs[k][28], xs[k][28]; activation loads are warp-uniform
// 16B broadcasts; weights [k][u][i,f,g,o] float4, 1 LDS.128 per k per warp.

#define NB 4096
#define TT 500
#define DD 32
#define HH 64
#define NGRID 152
#define NTHREADS 128
#define RMAX 28            // 27 real rows max + 1 pad

#define HS_F (HH * RMAX)   // 1792 floats per buffer
#define XS_F (DD * RMAX)   // 896 floats per buffer

#define SM_W4    0                      // float4 [96*64]  = 98304 B
#define SM_WOUT  98304                  // ull   [64*32]   = 16384 B (dup Wout)
#define SM_HS    114688                 // float [2][64][28] = 14336 B
#define SM_XS    129024                 // float [2][32][28] =  7168 B
#define SM_TOTAL 136192

typedef unsigned long long ull;

__device__ __forceinline__ ull pack2(float lo, float hi) {
    ull r; asm("mov.b64 %0, {%1, %2};" : "=l"(r) : "f"(lo), "f"(hi)); return r;
}
__device__ __forceinline__ void unpack2(float& lo, float& hi, ull v) {
    asm("mov.b64 {%0, %1}, %2;" : "=f"(lo), "=f"(hi) : "l"(v));
}
// Packed fp32x2 FMA (sm_100+; PTX-only)
#define FFMA2(acc, a, b) asm("fma.rn.f32x2 %0, %1, %2, %0;" : "+l"(acc) : "l"(a), "l"(b))

__device__ __forceinline__ float sigm(float v) {
    return __fdividef(1.f, 1.f + __expf(-v));
}
__device__ __forceinline__ float tanh_(float v) {
    return __fdividef(2.f, 1.f + __expf(-2.f * v)) - 1.f;
}

// One LSTM step for this thread's 14 rows (7 pairs).
// G0: rows 0-13 (Q0,Q4,Q8,P12); else rows 14-27 (P14,Q16,Q20,Q24).
template<bool G0>
__device__ __forceinline__ void gate_step(
    const float4* __restrict__ W4, const float* __restrict__ xsb,
    const float* __restrict__ hsb, float* __restrict__ hsn,
    const ull* bd, float* c, int u)
{
    constexpr int NP = 7;
    constexpr int base = G0 ? 0 : 14;
    ull ai[NP], af[NP], ag[NP], ao[NP];
#pragma unroll
    for (int p = 0; p < NP; ++p) { ai[p] = bd[0]; af[p] = bd[1]; ag[p] = bd[2]; ao[p] = bd[3]; }

#define GATE_K(KIDX, COL) {                                                   \
        float4 wq = W4[(KIDX) * 64 + u];                                      \
        ull wi2 = pack2(wq.x, wq.x), wf2 = pack2(wq.y, wq.y);                 \
        ull wg2 = pack2(wq.z, wq.z), wo2 = pack2(wq.w, wq.w);                 \
        ull hv[NP];                                                           \
        if constexpr (G0) {                                                   \
            ulonglong2 a = *reinterpret_cast<const ulonglong2*>((COL) + 0);   \
            ulonglong2 b = *reinterpret_cast<const ulonglong2*>((COL) + 4);   \
            ulonglong2 q = *reinterpret_cast<const ulonglong2*>((COL) + 8);   \
            ull pr = *reinterpret_cast<const ull*>((COL) + 12);               \
            hv[0] = a.x; hv[1] = a.y; hv[2] = b.x; hv[3] = b.y;               \
            hv[4] = q.x; hv[5] = q.y; hv[6] = pr;                             \
        } else {                                                              \
            ull pr = *reinterpret_cast<const ull*>((COL) + 14);               \
            ulonglong2 a = *reinterpret_cast<const ulonglong2*>((COL) + 16);  \
            ulonglong2 b = *reinterpret_cast<const ulonglong2*>((COL) + 20);  \
            ulonglong2 q = *reinterpret_cast<const ulonglong2*>((COL) + 24);  \
            hv[0] = pr; hv[1] = a.x; hv[2] = a.y; hv[3] = b.x;                \
            hv[4] = b.y; hv[5] = q.x; hv[6] = q.y;                            \
        }                                                                     \
        _Pragma("unroll")                                                     \
        for (int p = 0; p < NP; ++p) {                                        \
            FFMA2(ai[p], wi2, hv[p]);                                         \
            FFMA2(af[p], wf2, hv[p]);                                         \
            FFMA2(ag[p], wg2, hv[p]);                                         \
            FFMA2(ao[p], wo2, hv[p]);                                         \
        }                                                                     \
    }

#pragma unroll 8
    for (int k = 0; k < DD; ++k) GATE_K(k, xsb + k * RMAX)
#pragma unroll 8
    for (int k = 0; k < HH; ++k) GATE_K(DD + k, hsb + k * RMAX)
#undef GATE_K

#pragma unroll
    for (int p = 0; p < NP; ++p) {
        float i0, i1, f0, f1, g0, g1, o0, o1;
        unpack2(i0, i1, ai[p]);
        unpack2(f0, f1, af[p]);
        unpack2(g0, g1, ag[p]);
        unpack2(o0, o1, ao[p]);
        float cn0 = sigm(f0) * c[2 * p]     + sigm(i0) * tanh_(g0);
        float cn1 = sigm(f1) * c[2 * p + 1] + sigm(i1) * tanh_(g1);
        c[2 * p]     = cn0;
        c[2 * p + 1] = cn1;
        float h0 = sigm(o0) * tanh_(cn0);
        float h1 = sigm(o1) * tanh_(cn1);
        *reinterpret_cast<ull*>(hsn + u * RMAX + base + 2 * p) = pack2(h0, h1);
    }
}

__device__ __forceinline__ void load_gate_weights(
    float4* W4, const float* Wih, const float* Whh, int tid)
{
    for (int idx = tid; idx < 96 * 64; idx += NTHREADS) {
        int k = idx >> 6, uu = idx & 63;
        float4 w;
        if (k < DD) {
            w.x = Wih[(uu      ) * DD + k];
            w.y = Wih[(uu +  64) * DD + k];
            w.z = Wih[(uu + 128) * DD + k];
            w.w = Wih[(uu + 192) * DD + k];
        } else {
            int kk = k - DD;
            w.x = Whh[(uu      ) * HH + kk];
            w.y = Whh[(uu +  64) * HH + kk];
            w.z = Whh[(uu + 128) * HH + kk];
            w.w = Whh[(uu + 192) * HH + kk];
        }
        W4[idx] = w;
    }
}

// Decoder out-projection: k-outer, pairs inner.
template<int NRJ>
__device__ __forceinline__ void oproj_loop(
    ull* acc, const float* __restrict__ hsn, const ull* __restrict__ WoTd,
    const int* r2p, int dd)
{
#pragma unroll 8
    for (int k = 0; k < HH; ++k) {
        ull wv = WoTd[k * DD + dd];
#pragma unroll
        for (int j = 0; j < NRJ; ++j) {
            ull hv = *reinterpret_cast<const ull*>(hsn + k * RMAX + r2p[j]);
            FFMA2(acc[j], hv, wv);
        }
    }
}

__global__ void __launch_bounds__(NTHREADS, 1)
seq2seq_kernel(const float* __restrict__ x,
               const float* __restrict__ Wih_e, const float* __restrict__ Whh_e,
               const float* __restrict__ b_e,
               const float* __restrict__ Wih_d, const float* __restrict__ Whh_d,
               const float* __restrict__ b_d,
               const float* __restrict__ Wout, const float* __restrict__ bout,
               float* __restrict__ outp)
{
    extern __shared__ char sm[];
    float4* W4   = reinterpret_cast<float4*>(sm + SM_W4);
    ull*    WoTd = reinterpret_cast<ull*>(sm + SM_WOUT);
    float*  hsA  = reinterpret_cast<float*>(sm + SM_HS);   // [2][HS_F]
    float*  xsA  = reinterpret_cast<float*>(sm + SM_XS);   // [2][XS_F]

    const int tid = threadIdx.x;
    const int u   = tid & 63;
    const int grp = tid >> 6;      // 0 or 1
    const int bid = blockIdx.x;
    const int rstart = (bid * NB) / NGRID;
    const int cnt = ((bid + 1) * NB) / NGRID - rstart;     // 26 or 27

    // ---- encoder weights + state init ----
    load_gate_weights(W4, Wih_e, Whh_e, tid);
    for (int i = tid; i < 2 * HS_F; i += NTHREADS) hsA[i] = 0.f;
    for (int i = tid; i < XS_F; i += NTHREADS) {
        int r = i >> 5, d = i & 31;
        float v = 0.f;
        if (r < cnt) v = x[(size_t)(rstart + r) * (TT * DD) + d];   // t = 0
        xsA[d * RMAX + r] = v;                                      // buf 0, transposed
    }
    ull bd[4];
    bd[0] = pack2(b_e[u], b_e[u]);
    bd[1] = pack2(b_e[64 + u], b_e[64 + u]);
    bd[2] = pack2(b_e[128 + u], b_e[128 + u]);
    bd[3] = pack2(b_e[192 + u], b_e[192 + u]);
    float c_reg[14];
#pragma unroll
    for (int i = 0; i < 14; ++i) c_reg[i] = 0.f;

    // x prefetch slots: 7 x 128 = 896 = XS_F exactly
    const float* xp[7]; bool pval[7]; int poff[7];
#pragma unroll
    for (int s = 0; s < 7; ++s) {
        int i = tid + s * NTHREADS;
        int r = i >> 5, d = i & 31;
        int rc = (r < cnt) ? r : 0;
        pval[s] = (r < cnt);
        poff[s] = d * RMAX + r;
        xp[s] = x + (size_t)(rstart + rc) * (TT * DD) + DD + d;     // t = 1
    }
    __syncthreads();

    int cur = 0;
    // ===== encoder: 500 steps, 1 sync/step =====
    for (int t = 0; t < TT; ++t) {
        const int nxt = cur ^ 1;
        float xv[7];
        const bool pre = (t + 1 < TT);
        if (pre) {
#pragma unroll
            for (int s = 0; s < 7; ++s) xv[s] = pval[s] ? *xp[s] : 0.f;
        }
        const float* xsb = xsA + cur * XS_F;
        const float* hsb = hsA + cur * HS_F;
        float*       hsn = hsA + nxt * HS_F;
        if (grp == 0) gate_step<true >(W4, xsb, hsb, hsn, bd, c_reg, u);
        else          gate_step<false>(W4, xsb, hsb, hsn, bd, c_reg, u);
        if (pre) {
            float* xsn = xsA + nxt * XS_F;
#pragma unroll
            for (int s = 0; s < 7; ++s) {
                xsn[poff[s]] = xv[s];
                xp[s] += DD;
            }
        }
        __syncthreads();
        cur = nxt;
    }

    // ===== swap to decoder weights =====
    load_gate_weights(W4, Wih_d, Whh_d, tid);
    for (int idx = tid; idx < HH * DD; idx += NTHREADS) {
        int k = idx >> 5, d = idx & 31;
        float w = Wout[d * HH + k];
        WoTd[idx] = pack2(w, w);           // WoTd[k*32+d] = (w, w)
    }
    for (int i = tid; i < XS_F; i += NTHREADS)
        xsA[cur * XS_F + i] = 0.f;          // dec_in0 = 0
    bd[0] = pack2(b_d[u], b_d[u]);
    bd[1] = pack2(b_d[64 + u], b_d[64 + u]);
    bd[2] = pack2(b_d[128 + u], b_d[128 + u]);
    bd[3] = pack2(b_d[192 + u], b_d[192 + u]);

    // out-projection: slot = grp*2 + half (0..3) owns pairs {slot + 4j}
    const int dd   = u & 31;
    const int half = u >> 5;
    const int slot = grp * 2 + half;
    const int nrj  = (slot < 2) ? 4 : 3;    // pairs 0..13 covered exactly once
    const float bo = bout[dd];
    bool ov0[4], ov1[4]; float* o0p[4]; float* o1p[4];
    int r2p[4]; int xoff[4];
#pragma unroll
    for (int j = 0; j < 4; ++j) {
        int p = slot + 4 * j;
        bool v = (j < nrj);
        int r0 = v ? 2 * p : 0;
        r2p[j]  = r0;
        ov0[j] = v && (r0 < cnt);
        ov1[j] = v && (r0 + 1 < cnt);
        o0p[j] = outp + (size_t)(rstart + r0) * (TT * DD) + dd;
        o1p[j] = outp + (size_t)(rstart + r0 + 1) * (TT * DD) + dd;
        xoff[j] = dd * RMAX + r0;
    }
    __syncthreads();

    // ===== decoder: 500 autoregressive steps, 2 syncs/step =====
    for (int t = 0; t < TT; ++t) {
        const int nxt = cur ^ 1;
        const float* xsb = xsA + cur * XS_F;
        const float* hsb = hsA + cur * HS_F;
        float*       hsn = hsA + nxt * HS_F;
        if (grp == 0) gate_step<true >(W4, xsb, hsb, hsn, bd, c_reg, u);
        else          gate_step<false>(W4, xsb, hsb, hsn, bd, c_reg, u);
        __syncthreads();

        // out = h @ Wout^T + bout (row-pair packed), feeds next x
        {
            float* xsn = xsA + nxt * XS_F;
            ull acc[4];
#pragma unroll
            for (int j = 0; j < 4; ++j) acc[j] = pack2(bo, bo);
            if (nrj == 4) oproj_loop<4>(acc, hsn, WoTd, r2p, dd);
            else          oproj_loop<3>(acc, hsn, WoTd, r2p, dd);
#pragma unroll
            for (int j = 0; j < 4; ++j) {
                if (j >= nrj) break;       // warp-uniform
                float o0, o1; unpack2(o0, o1, acc[j]);
                if (ov0[j]) *o0p[j] = o0;
                if (ov1[j]) *o1p[j] = o1;
                o0p[j] += DD; o1p[j] += DD;
                *reinterpret_cast<ull*>(xsn + xoff[j]) = pack2(o0, o1);
            }
        }
        __syncthreads();
        cur = nxt;
    }
}

extern "C" void kernel_launch(void* const* d_in, const int* in_sizes, int n_in,
                              void* d_out, int out_size)
{
    (void)in_sizes; (void)n_in; (void)out_size;
    cudaFuncSetAttribute(seq2seq_kernel,
                         cudaFuncAttributeMaxDynamicSharedMemorySize, SM_TOTAL);
    seq2seq_kernel<<<NGRID, NTHREADS, SM_TOTAL>>>(
        (const float*)d_in[0],
        (const float*)d_in[1], (const float*)d_in[2], (const float*)d_in[3],
        (const float*)d_in[4], (const float*)d_in[5], (const float*)d_in[6],
        (const float*)d_in[7], (const float*)d_in[8],
        (float*)d_out);
}